// round 16
// baseline (speedup 1.0000x reference)
#include <cuda_runtime.h>
#include <cuda_fp16.h>
#include <cstdint>

#define NODES_CAP 50000
#define BUCKET_CAP 64

// Scratch (no allocations allowed -> __device__ globals)
__device__ uint2 g_feat16[(size_t)NODES_CAP * 32];   // feat fp16 hi, row-major [N][128]
__device__ uint2 g_featlo[(size_t)NODES_CAP * 32];   // feat fp16 lo residual
__device__ uint2 g_nhi[(size_t)NODES_CAP * 32];      // neigh fp16 hi
__device__ uint2 g_nlo[(size_t)NODES_CAP * 32];      // neigh fp16 lo
__device__ int g_cnt[NODES_CAP];
__device__ unsigned long long g_bucket[(size_t)NODES_CAP * BUCKET_CAP];  // (w<<32)|src
__device__ __half g_wh[128 * 256];   // combined W^T, n-major [n][k], fp16 hi
__device__ __half g_wl[128 * 256];   // fp16 lo residual
__device__ float g_colsum[128];
__device__ float g_colsq[128];

__device__ __forceinline__ unsigned h2_to_u32(__half2 h) {
    union { __half2 h; unsigned u; } cv;
    cv.h = h;
    return cv.u;
}

__device__ __forceinline__ float2 u32_to_f2(unsigned u) {
    union { unsigned u; __half2 h; } cv;
    cv.u = u;
    return __half22float2(cv.h);
}

__device__ __forceinline__ void split_f16(float v, __half& hi, __half& lo) {
    hi = __float2half_rn(v);
    lo = __float2half_rn(v - __half2float(hi));
}

__device__ __forceinline__ unsigned smem_u32(const void* p) {
    return (unsigned)__cvta_generic_to_shared(p);
}

#define LDSM_X4(d0, d1, d2, d3, addr) \
    asm volatile("ldmatrix.sync.aligned.m8n8.x4.shared.b16 {%0,%1,%2,%3}, [%4];" \
                 : "=r"(d0), "=r"(d1), "=r"(d2), "=r"(d3) : "r"(addr))

// ---------------------------------------------------------------------------
// Prep (fused): zero counters/stats + feat->fp16 hi/lo + weight fp16 split
// ---------------------------------------------------------------------------
__global__ __launch_bounds__(256) void prep(
    const float* __restrict__ feat,
    const float* __restrict__ Wn, const float* __restrict__ Ws,
    int N, long tot4)
{
    long i = (long)blockIdx.x * blockDim.x + threadIdx.x;
    if (i < tot4) {
        float4 v = reinterpret_cast<const float4*>(feat)[i];
        __half h0, h1, h2, h3, l0, l1, l2, l3;
        split_f16(v.x, h0, l0); split_f16(v.y, h1, l1);
        split_f16(v.z, h2, l2); split_f16(v.w, h3, l3);
        uint2 ph, pl;
        ph.x = h2_to_u32(__halves2half2(h0, h1));
        ph.y = h2_to_u32(__halves2half2(h2, h3));
        pl.x = h2_to_u32(__halves2half2(l0, l1));
        pl.y = h2_to_u32(__halves2half2(l2, l3));
        g_feat16[i] = ph;
        g_featlo[i] = pl;
    }
    if (i < N) g_cnt[i] = 0;
    if (i < 128) { g_colsum[i] = 0.f; g_colsq[i] = 0.f; }
    if (i < 128 * 256) {
        int n = (int)i >> 8, k = (int)i & 255;
        float v = (k < 128) ? Ws[n * 128 + k] : Wn[n * 128 + (k - 128)];
        __half hi, lo;
        split_f16(v, hi, lo);
        g_wh[i] = hi;
        g_wl[i] = lo;
    }
}

// ---------------------------------------------------------------------------
// Phase A: bin edges into per-dst buckets. 4 edges per thread (ILP).
// ---------------------------------------------------------------------------
__global__ __launch_bounds__(256) void edge_bin(
    const int* __restrict__ src, const int* __restrict__ dst,
    const float* __restrict__ ew, int E)
{
    int t = blockIdx.x * blockDim.x + threadIdx.x;
    int e0 = t * 4;
    if (e0 >= E) return;
    if (e0 + 3 < E) {
        int4 s4 = *reinterpret_cast<const int4*>(src + e0);
        int4 d4 = *reinterpret_cast<const int4*>(dst + e0);
        float4 w4 = *reinterpret_cast<const float4*>(ew + e0);
        int p0 = atomicAdd(g_cnt + d4.x, 1);
        int p1 = atomicAdd(g_cnt + d4.y, 1);
        int p2 = atomicAdd(g_cnt + d4.z, 1);
        int p3 = atomicAdd(g_cnt + d4.w, 1);
        if (p0 < BUCKET_CAP)
            g_bucket[(long)d4.x * BUCKET_CAP + p0] =
                ((unsigned long long)__float_as_uint(w4.x) << 32) | (unsigned)s4.x;
        if (p1 < BUCKET_CAP)
            g_bucket[(long)d4.y * BUCKET_CAP + p1] =
                ((unsigned long long)__float_as_uint(w4.y) << 32) | (unsigned)s4.y;
        if (p2 < BUCKET_CAP)
            g_bucket[(long)d4.z * BUCKET_CAP + p2] =
                ((unsigned long long)__float_as_uint(w4.z) << 32) | (unsigned)s4.z;
        if (p3 < BUCKET_CAP)
            g_bucket[(long)d4.w * BUCKET_CAP + p3] =
                ((unsigned long long)__float_as_uint(w4.w) << 32) | (unsigned)s4.w;
    } else {
        for (int e = e0; e < E; e++) {
            int d = __ldg(dst + e);
            int s = __ldg(src + e);
            unsigned w = __float_as_uint(__ldg(ew + e));
            int pos = atomicAdd(g_cnt + d, 1);
            if (pos < BUCKET_CAP)
                g_bucket[(long)d * BUCKET_CAP + pos] =
                    ((unsigned long long)w << 32) | (unsigned)s;
        }
    }
}

// ---------------------------------------------------------------------------
// Phase B: one warp per dst. fp16 gather, fp32 accumulate, normalize, write
// neigh as fp16 hi/lo.
// ---------------------------------------------------------------------------
__global__ __launch_bounds__(256) void node_aggregate(int N)
{
    int warp = (blockIdx.x * blockDim.x + threadIdx.x) >> 5;
    int lane = threadIdx.x & 31;
    if (warp >= N) return;
    int cnt = g_cnt[warp];
    if (cnt > BUCKET_CAP) cnt = BUCKET_CAP;
    const unsigned long long* bk = g_bucket + (long)warp * BUCKET_CAP;

    float4 acc = make_float4(0.f, 0.f, 0.f, 0.f);
    float wsum = 0.f;
    int e = 0;
    for (; e + 1 < cnt; e += 2) {
        unsigned long long p0 = bk[e];
        unsigned long long p1 = bk[e + 1];
        int s0 = (int)(unsigned)p0;
        int s1 = (int)(unsigned)p1;
        float w0 = __uint_as_float((unsigned)(p0 >> 32));
        float w1 = __uint_as_float((unsigned)(p1 >> 32));
        uint2 q0 = g_feat16[(long)s0 * 32 + lane];
        uint2 q1 = g_feat16[(long)s1 * 32 + lane];
        float2 a0 = u32_to_f2(q0.x);
        float2 b0 = u32_to_f2(q0.y);
        float2 a1 = u32_to_f2(q1.x);
        float2 b1 = u32_to_f2(q1.y);
        acc.x = fmaf(w0, a0.x, acc.x); acc.y = fmaf(w0, a0.y, acc.y);
        acc.z = fmaf(w0, b0.x, acc.z); acc.w = fmaf(w0, b0.y, acc.w);
        acc.x = fmaf(w1, a1.x, acc.x); acc.y = fmaf(w1, a1.y, acc.y);
        acc.z = fmaf(w1, b1.x, acc.z); acc.w = fmaf(w1, b1.y, acc.w);
        wsum += w0 + w1;
    }
    if (e < cnt) {
        unsigned long long p0 = bk[e];
        int s0 = (int)(unsigned)p0;
        float w0 = __uint_as_float((unsigned)(p0 >> 32));
        uint2 q0 = g_feat16[(long)s0 * 32 + lane];
        float2 a0 = u32_to_f2(q0.x);
        float2 b0 = u32_to_f2(q0.y);
        acc.x = fmaf(w0, a0.x, acc.x); acc.y = fmaf(w0, a0.y, acc.y);
        acc.z = fmaf(w0, b0.x, acc.z); acc.w = fmaf(w0, b0.y, acc.w);
        wsum += w0;
    }
    float inv = 1.f / (wsum + 1e-8f);
    acc.x *= inv; acc.y *= inv; acc.z *= inv; acc.w *= inv;
    __half h0, h1, h2, h3, l0, l1, l2, l3;
    split_f16(acc.x, h0, l0); split_f16(acc.y, h1, l1);
    split_f16(acc.z, h2, l2); split_f16(acc.w, h3, l3);
    uint2 ph, pl;
    ph.x = h2_to_u32(__halves2half2(h0, h1));
    ph.y = h2_to_u32(__halves2half2(h2, h3));
    pl.x = h2_to_u32(__halves2half2(l0, l1));
    pl.y = h2_to_u32(__halves2half2(l2, l3));
    g_nhi[(long)warp * 32 + lane] = ph;
    g_nlo[(long)warp * 32 + lane] = pl;
}

// ---------------------------------------------------------------------------
// Tensor-core GEMM (3xFP16 m16n8k16) with ldmatrix fragment loads.
// Block: 64 rows x 128 cols, 128 threads (4 warps); warp w owns cols [w*32,+32).
// B is n-major in smem -> plain (non-trans) ldmatrix yields the B fragment
// (thread t holds B[n=t/4][k=(t%4)*2+{0,1}]).
// Smem pitch 72 halves (36 words): 8-row LDSM groups step 4 banks -> conflict-free.
// Epilogue accumulates BN column stats. Dynamic smem 56320 B.
// ---------------------------------------------------------------------------
// word-offsets: AHI 0 (64x36), ALO 2304, BHI 4608 (128x36), BLO 9216;
// float stats: sS @13824, sQ @13952. Total 14080 words.
#define W_AHI 0
#define W_ALO 2304
#define W_BHI 4608
#define W_BLO 9216
#define W_SS 13824
#define W_SQ 13952
#define SMEM_BYTES (14080 * 4)

__global__ __launch_bounds__(128) void gemm_tc(
    const float* __restrict__ b_self,
    const float* __restrict__ bias,
    float* __restrict__ out, int N)
{
    extern __shared__ __align__(16) unsigned smw[];
    float* smf = reinterpret_cast<float*>(smw);

    const int tid = threadIdx.x;
    const int warp = tid >> 5;
    const int lane = tid & 31;
    const int row0 = blockIdx.x * 64;
    const int n0w = warp * 32;
    const int lq = lane >> 2;   // 0..7
    const int lr = lane & 3;    // 0..3

    if (tid < 128) { smf[W_SS + tid] = 0.f; smf[W_SQ + tid] = 0.f; }

    // ldmatrix lane-address components:
    //   A (x4): lanes 0-7 -> rows 0-7 k+0 (a0); 8-15 -> rows 8-15 k+0 (a1);
    //           16-23 -> rows 0-7 k+8 (a2); 24-31 -> rows 8-15 k+8 (a3)
    const int a_row = lane & 15;
    const int a_kh = lane >> 4;        // 0/1 -> +0/+4 words (8 halves)
    //   B (x4, non-trans): lanes 0-7 -> n rows 0-7 k+0 (b0 strip0);
    //     8-15 -> n rows 0-7 k+8 (b1 strip0); 16-23 -> n rows 8-15 k+0 (b0 strip1);
    //     24-31 -> n rows 8-15 k+8 (b1 strip1)
    const int b_nrow = ((lane >> 4) * 8) + (lane & 7);
    const int b_kh = (lane >> 3) & 1;

    float C[4][4][4];
#pragma unroll
    for (int mt = 0; mt < 4; mt++)
#pragma unroll
        for (int nt = 0; nt < 4; nt++)
#pragma unroll
            for (int j = 0; j < 4; j++) C[mt][nt][j] = 0.f;

    for (int kt = 0; kt < 4; kt++) {
        __syncthreads();
        // A tile: 64 rows x 64 k fp16 (hi+lo). Source: feat (kt<2) or neigh.
        const uint4* AH = (kt < 2) ? reinterpret_cast<const uint4*>(g_feat16)
                                   : reinterpret_cast<const uint4*>(g_nhi);
        const uint4* AL = (kt < 2) ? reinterpret_cast<const uint4*>(g_featlo)
                                   : reinterpret_cast<const uint4*>(g_nlo);
        int kofs8 = (kt & 1) * 8;   // uint4 offset within row (8 halves each)
#pragma unroll
        for (int i = 0; i < 4; i++) {
            int idx = tid + i * 128;      // 0..511
            int r = idx >> 3;
            int c8 = idx & 7;
            uint4 vh = make_uint4(0, 0, 0, 0), vl = vh;
            int gr = row0 + r;
            if (gr < N) {
                vh = AH[gr * 16 + kofs8 + c8];
                vl = AL[gr * 16 + kofs8 + c8];
            }
            *reinterpret_cast<uint4*>(smw + W_AHI + r * 36 + c8 * 4) = vh;
            *reinterpret_cast<uint4*>(smw + W_ALO + r * 36 + c8 * 4) = vl;
        }
        // B tile: 128 n x 64 k fp16 (hi+lo), n-major gmem [n][256]
        int kb8 = kt * 8;
#pragma unroll
        for (int i = 0; i < 8; i++) {
            int idx = tid + i * 128;      // 0..1023
            int n = idx >> 3;
            int c8 = idx & 7;
            uint4 vh = reinterpret_cast<const uint4*>(g_wh)[n * 32 + kb8 + c8];
            uint4 vl = reinterpret_cast<const uint4*>(g_wl)[n * 32 + kb8 + c8];
            *reinterpret_cast<uint4*>(smw + W_BHI + n * 36 + c8 * 4) = vh;
            *reinterpret_cast<uint4*>(smw + W_BLO + n * 36 + c8 * 4) = vl;
        }
        __syncthreads();

#pragma unroll
        for (int k16 = 0; k16 < 4; k16++) {
            int kb = k16 * 8;   // word base within row
            unsigned ah[4][4], al[4][4];
#pragma unroll
            for (int mt = 0; mt < 4; mt++) {
                int aw = (mt * 16 + a_row) * 36 + kb + a_kh * 4;
                unsigned ad = smem_u32(&smw[W_AHI + aw]);
                LDSM_X4(ah[mt][0], ah[mt][1], ah[mt][2], ah[mt][3], ad);
                unsigned ad2 = smem_u32(&smw[W_ALO + aw]);
                LDSM_X4(al[mt][0], al[mt][1], al[mt][2], al[mt][3], ad2);
            }
            unsigned bh[4][2], bl[4][2];
#pragma unroll
            for (int p = 0; p < 2; p++) {
                int bw = (n0w + p * 16 + b_nrow) * 36 + kb + b_kh * 4;
                unsigned bd = smem_u32(&smw[W_BHI + bw]);
                LDSM_X4(bh[p * 2][0], bh[p * 2][1], bh[p * 2 + 1][0], bh[p * 2 + 1][1], bd);
                unsigned bd2 = smem_u32(&smw[W_BLO + bw]);
                LDSM_X4(bl[p * 2][0], bl[p * 2][1], bl[p * 2 + 1][0], bl[p * 2 + 1][1], bd2);
            }
#pragma unroll
            for (int nt = 0; nt < 4; nt++) {
#pragma unroll
                for (int mt = 0; mt < 4; mt++) {
                    float* c = C[mt][nt];
                    asm volatile(
                        "mma.sync.aligned.m16n8k16.row.col.f32.f16.f16.f32 "
                        "{%0,%1,%2,%3}, {%4,%5,%6,%7}, {%8,%9}, {%0,%1,%2,%3};"
                        : "+f"(c[0]), "+f"(c[1]), "+f"(c[2]), "+f"(c[3])
                        : "r"(ah[mt][0]), "r"(ah[mt][1]), "r"(ah[mt][2]), "r"(ah[mt][3]),
                          "r"(bh[nt][0]), "r"(bh[nt][1]));
                    asm volatile(
                        "mma.sync.aligned.m16n8k16.row.col.f32.f16.f16.f32 "
                        "{%0,%1,%2,%3}, {%4,%5,%6,%7}, {%8,%9}, {%0,%1,%2,%3};"
                        : "+f"(c[0]), "+f"(c[1]), "+f"(c[2]), "+f"(c[3])
                        : "r"(ah[mt][0]), "r"(ah[mt][1]), "r"(ah[mt][2]), "r"(ah[mt][3]),
                          "r"(bl[nt][0]), "r"(bl[nt][1]));
                    asm volatile(
                        "mma.sync.aligned.m16n8k16.row.col.f32.f16.f16.f32 "
                        "{%0,%1,%2,%3}, {%4,%5,%6,%7}, {%8,%9}, {%0,%1,%2,%3};"
                        : "+f"(c[0]), "+f"(c[1]), "+f"(c[2]), "+f"(c[3])
                        : "r"(al[mt][0]), "r"(al[mt][1]), "r"(al[mt][2]), "r"(al[mt][3]),
                          "r"(bh[nt][0]), "r"(bh[nt][1]));
                }
            }
        }
    }

    // Epilogue: bias + ReLU, write, accumulate BN column stats.
    // C layout: c0:(r=lq, c=lr*2) c1:(r, c+1) c2:(r+8, c) c3:(r+8, c+1)
#pragma unroll
    for (int nt = 0; nt < 4; nt++) {
        int c = n0w + nt * 8 + lr * 2;
        float bc0 = __ldg(b_self + c) + __ldg(bias + c);
        float bc1 = __ldg(b_self + c + 1) + __ldg(bias + c + 1);
        float s0 = 0.f, s1 = 0.f, q0 = 0.f, q1 = 0.f;
#pragma unroll
        for (int mt = 0; mt < 4; mt++) {
            int r = row0 + mt * 16 + lq;
            if (r < N) {
                float v0 = fmaxf(C[mt][nt][0] + bc0, 0.f);
                float v1 = fmaxf(C[mt][nt][1] + bc1, 0.f);
                *reinterpret_cast<float2*>(out + (long)r * 128 + c) = make_float2(v0, v1);
                s0 += v0; s1 += v1;
                q0 = fmaf(v0, v0, q0); q1 = fmaf(v1, v1, q1);
            }
            if (r + 8 < N) {
                float v2 = fmaxf(C[mt][nt][2] + bc0, 0.f);
                float v3 = fmaxf(C[mt][nt][3] + bc1, 0.f);
                *reinterpret_cast<float2*>(out + (long)(r + 8) * 128 + c) = make_float2(v2, v3);
                s0 += v2; s1 += v3;
                q0 = fmaf(v2, v2, q0); q1 = fmaf(v3, v3, q1);
            }
        }
        atomicAdd(&smf[W_SS + c], s0); atomicAdd(&smf[W_SS + c + 1], s1);
        atomicAdd(&smf[W_SQ + c], q0); atomicAdd(&smf[W_SQ + c + 1], q1);
    }
    __syncthreads();
    if (tid < 128) {
        atomicAdd(g_colsum + tid, smf[W_SS + tid]);
        atomicAdd(g_colsq + tid, smf[W_SQ + tid]);
    }
}

// ---------------------------------------------------------------------------
// BatchNorm apply (finalize folded in; every block recomputes scale/shift)
// ---------------------------------------------------------------------------
__global__ __launch_bounds__(256) void bn_apply(
    float* __restrict__ out,
    const float* __restrict__ gamma, const float* __restrict__ beta,
    float invN, long tot4)
{
    __shared__ float sc[128];
    __shared__ float sh[128];
    int tid = threadIdx.x;
    if (tid < 128) {
        float mu = g_colsum[tid] * invN;
        float var = g_colsq[tid] * invN - mu * mu;
        float s = rsqrtf(var + 1e-5f) * gamma[tid];
        sc[tid] = s;
        sh[tid] = beta[tid] - mu * s;
    }
    __syncthreads();
    long i = (long)blockIdx.x * blockDim.x + tid;
    if (i >= tot4) return;
    float4 v = reinterpret_cast<float4*>(out)[i];
    int c0 = (int)(i & 31) * 4;
    v.x = v.x * sc[c0 + 0] + sh[c0 + 0];
    v.y = v.y * sc[c0 + 1] + sh[c0 + 1];
    v.z = v.z * sc[c0 + 2] + sh[c0 + 2];
    v.w = v.w * sc[c0 + 3] + sh[c0 + 3];
    reinterpret_cast<float4*>(out)[i] = v;
}

// ---------------------------------------------------------------------------
extern "C" void kernel_launch(void* const* d_in, const int* in_sizes, int n_in,
                              void* d_out, int out_size) {
    const float* feat   = (const float*)d_in[0];
    const int*   src    = (const int*)  d_in[1];
    const int*   dst    = (const int*)  d_in[2];
    const float* ew     = (const float*)d_in[3];
    const float* Wn     = (const float*)d_in[4];
    const float* Ws     = (const float*)d_in[5];
    const float* b_self = (const float*)d_in[6];
    const float* bias   = (const float*)d_in[7];
    const float* gamma  = (const float*)d_in[8];
    const float* beta   = (const float*)d_in[9];
    float* out = (float*)d_out;

    int N = in_sizes[0] / 128;
    int E = in_sizes[1];
    long tot4 = (long)N * 32;

    cudaFuncSetAttribute(gemm_tc, cudaFuncAttributeMaxDynamicSharedMemorySize, SMEM_BYTES);

    prep<<<(int)((tot4 + 255) / 256), 256>>>(feat, Wn, Ws, N, tot4);
    edge_bin<<<(E / 4 + 255) / 256, 256>>>(src, dst, ew, E);
    node_aggregate<<<(N + 7) / 8, 256>>>(N);
    gemm_tc<<<(N + 63) / 64, 128, SMEM_BYTES>>>(b_self, bias, out, N);
    bn_apply<<<(int)((tot4 + 255) / 256), 256>>>(out, gamma, beta, 1.0f / (float)N, tot4);
}